// round 2
// baseline (speedup 1.0000x reference)
#include <cuda_runtime.h>
#include <cfloat>

// 101-layer chain h <- relu(w*h + b), w > 0, collapses exactly to
//   f(x) = S * max(x, C) + O
// (clamp-below composed with positive affine stays a single clamp-below).
//
// Single fused kernel: thread 0 of each block runs the 101-step scalar scan
// (404 B of w/b, L2-hot after the first block; ~3.5k dependent cycles,
// concurrent across all resident blocks => ~1.7us wall once), broadcasts
// (S,C,O) through shared memory, then the whole block streams float4 with
// a 4-way-unrolled grid-stride loop using streaming load/store hints.

__global__ __launch_bounds__(256, 8)
void fused_chain_kernel(const float* __restrict__ x,
                        float* __restrict__ out,
                        const float* __restrict__ w,
                        const float* __restrict__ b,
                        int n_layers, int n4, int n) {
    __shared__ float sS, sC, sO;

    if (threadIdx.x == 0) {
        float S = 1.0f;
        float O = 0.0f;
        float C = -FLT_MAX;
        for (int i = 0; i < n_layers; ++i) {
            float wi = w[i];
            float bi = b[i];
            S = wi * S;
            O = fmaf(wi, O, bi);
            // layer i requires S*x + O >= 0  =>  x >= -O/S   (S > 0)
            C = fmaxf(C, -__fdividef(O, S));
        }
        sS = S;
        sC = C;
        sO = O;
    }
    __syncthreads();

    const float S = sS;
    const float C = sC;
    const float O = sO;

    const float4* __restrict__ x4 = (const float4*)x;
    float4* __restrict__ o4 = (float4*)out;

    const int tid    = blockIdx.x * blockDim.x + threadIdx.x;
    const int stride = gridDim.x * blockDim.x;

    int i = tid;
    // 4-way unrolled main loop: 4 independent LDG.128 in flight per thread
    for (; i + 3 * stride < n4; i += 4 * stride) {
        float4 v0 = __ldcs(x4 + i);
        float4 v1 = __ldcs(x4 + i + stride);
        float4 v2 = __ldcs(x4 + i + 2 * stride);
        float4 v3 = __ldcs(x4 + i + 3 * stride);

        float4 r0, r1, r2, r3;
        r0.x = fmaf(S, fmaxf(v0.x, C), O); r0.y = fmaf(S, fmaxf(v0.y, C), O);
        r0.z = fmaf(S, fmaxf(v0.z, C), O); r0.w = fmaf(S, fmaxf(v0.w, C), O);
        r1.x = fmaf(S, fmaxf(v1.x, C), O); r1.y = fmaf(S, fmaxf(v1.y, C), O);
        r1.z = fmaf(S, fmaxf(v1.z, C), O); r1.w = fmaf(S, fmaxf(v1.w, C), O);
        r2.x = fmaf(S, fmaxf(v2.x, C), O); r2.y = fmaf(S, fmaxf(v2.y, C), O);
        r2.z = fmaf(S, fmaxf(v2.z, C), O); r2.w = fmaf(S, fmaxf(v2.w, C), O);
        r3.x = fmaf(S, fmaxf(v3.x, C), O); r3.y = fmaf(S, fmaxf(v3.y, C), O);
        r3.z = fmaf(S, fmaxf(v3.z, C), O); r3.w = fmaf(S, fmaxf(v3.w, C), O);

        __stcs(o4 + i,              r0);
        __stcs(o4 + i + stride,     r1);
        __stcs(o4 + i + 2 * stride, r2);
        __stcs(o4 + i + 3 * stride, r3);
    }
    // remainder
    for (; i < n4; i += stride) {
        float4 v = __ldcs(x4 + i);
        float4 r;
        r.x = fmaf(S, fmaxf(v.x, C), O);
        r.y = fmaf(S, fmaxf(v.y, C), O);
        r.z = fmaf(S, fmaxf(v.z, C), O);
        r.w = fmaf(S, fmaxf(v.w, C), O);
        __stcs(o4 + i, r);
    }
    // scalar tail (n % 4 != 0)
    if (tid == 0) {
        for (int j = n4 * 4; j < n; ++j) {
            out[j] = fmaf(S, fmaxf(x[j], C), O);
        }
    }
}

extern "C" void kernel_launch(void* const* d_in, const int* in_sizes, int n_in,
                              void* d_out, int out_size) {
    const float* x = (const float*)d_in[0];
    const float* w = (const float*)d_in[1];
    const float* b = (const float*)d_in[2];
    float* out = (float*)d_out;

    const int n        = in_sizes[0];
    const int n_layers = in_sizes[1];
    const int n4       = n / 4;

    // One full resident wave: 148 SMs x 8 blocks x 256 threads
    const int threads = 256;
    const int blocks  = 148 * 8;

    fused_chain_kernel<<<blocks, threads>>>(x, out, w, b, n_layers, n4, n);
}

// round 3
// speedup vs baseline: 1.0424x; 1.0424x over previous
#include <cuda_runtime.h>
#include <cfloat>

// 101-layer chain h <- relu(w*h + b), w > 0, collapses exactly to
//   f(x) = S * max(x, C) + O.
// The per-prefix triple (S, C, O) composes ASSOCIATIVELY:
//   (g o f): S = Sg*Sf,  C = max(Cf, (Cg - Of)/Sf),  O = Sg*Of + Og
// so warp 0 of each block computes it with a parallel-load + shuffle scan
// (~0.3us, one resident wave of persistent blocks), then the whole block
// streams float4 with a software-pipelined contiguous-chunk loop.

__global__ __launch_bounds__(256, 8)
void fused_chain_kernel(const float4* __restrict__ x4,
                        float4* __restrict__ o4,
                        const float* __restrict__ w,
                        const float* __restrict__ b,
                        int n_layers, int n4, int n, int chunk,
                        const float* __restrict__ x,
                        float* __restrict__ out) {
    __shared__ float sS, sC, sO;

    const int tid = threadIdx.x;

    // Contiguous chunk per block; prefetch first element BEFORE the scan
    // barrier so its DRAM latency hides under the scan.
    int i = blockIdx.x * chunk + tid;
    const int iend = min(blockIdx.x * chunk + chunk, n4);
    bool valid = (i < iend);
    float4 v;
    if (valid) v = x4[i];

    // ---- warp 0: parallel-load + shuffle scan over (up to) 128 layers ----
    if (tid < 32) {
        const int l = tid;
        float S = 1.0f, C = -FLT_MAX, O = 0.0f;
        // local fold of 4 layers (loads are independent -> full MLP)
        #pragma unroll
        for (int k = 0; k < 4; ++k) {
            const int idx = 4 * l + k;
            if (idx < n_layers) {
                const float wi = w[idx];
                const float bi = b[idx];
                const float Cl = __fdividef(-bi, wi);           // layer clamp
                C = fmaxf(C, __fdividef(Cl - O, S));
                S = wi * S;
                O = fmaf(wi, O, bi);
            }
        }
        // inclusive Hillis-Steele scan with the composition operator
        #pragma unroll
        for (int d = 1; d < 32; d <<= 1) {
            const float Sp = __shfl_up_sync(0xffffffffu, S, d);
            const float Cp = __shfl_up_sync(0xffffffffu, C, d);
            const float Op = __shfl_up_sync(0xffffffffu, O, d);
            if (l >= d) {
                C = fmaxf(Cp, __fdividef(C - Op, Sp));
                O = fmaf(S, Op, O);   // uses my old S
                S = S * Sp;
            }
        }
        if (l == 31) { sS = S; sC = C; sO = O; }
    }
    __syncthreads();

    const float S = sS;
    const float C = sC;
    const float O = sO;

    // ---- software-pipelined streaming loop (load i+1 before store i) ----
    while (valid) {
        const int inext = i + 256;
        const bool vnext = (inext < iend);
        float4 vn;
        if (vnext) vn = x4[inext];

        float4 r;
        r.x = fmaf(S, fmaxf(v.x, C), O);
        r.y = fmaf(S, fmaxf(v.y, C), O);
        r.z = fmaf(S, fmaxf(v.z, C), O);
        r.w = fmaf(S, fmaxf(v.w, C), O);
        o4[i] = r;

        v = vn; i = inext; valid = vnext;
    }

    // scalar tail (n % 4 != 0) — one thread, negligible
    if (blockIdx.x == 0 && tid == 0) {
        for (int j = n4 * 4; j < n; ++j) {
            out[j] = fmaf(S, fmaxf(x[j], C), O);
        }
    }
}

extern "C" void kernel_launch(void* const* d_in, const int* in_sizes, int n_in,
                              void* d_out, int out_size) {
    const float* x = (const float*)d_in[0];
    const float* w = (const float*)d_in[1];
    const float* b = (const float*)d_in[2];
    float* out = (float*)d_out;

    const int n        = in_sizes[0];
    const int n_layers = in_sizes[1];
    const int n4       = n / 4;

    // One resident wave of persistent blocks: 148 SMs x 8 blocks x 256 thr
    const int threads = 256;
    const int blocks  = 148 * 8;
    const int chunk   = (n4 + blocks - 1) / blocks;

    fused_chain_kernel<<<blocks, threads>>>(
        (const float4*)x, (float4*)out, w, b,
        n_layers, n4, n, chunk, x, out);
}

// round 4
// speedup vs baseline: 1.1413x; 1.0949x over previous
#include <cuda_runtime.h>
#include <cfloat>

// 101-layer chain h <- relu(w*h + b), w > 0, collapses exactly to
//   f(x) = S * max(x, C) + O.
// The prefix triple (S, C, O) composes associatively:
//   (g o f): S = Sg*Sf,  C = max(Cf, (Cg - Of)/Sf),  O = Sg*Of + Og.
//
// Structure (fastest observed across R1-R3):
//   - FLAT grid, exactly one float4 per thread (R1's stream: 71.7% DRAM),
//   - per-block warp-0 shuffle scan (R3), hidden under each thread's
//     prefetched gmem load, broadcast via shared memory, one barrier.

__global__ __launch_bounds__(256, 8)
void fused_flat_kernel(const float4* __restrict__ x4,
                       float4* __restrict__ o4,
                       const float* __restrict__ w,
                       const float* __restrict__ b,
                       int n_layers, int n4, int n,
                       const float* __restrict__ x,
                       float* __restrict__ out) {
    __shared__ float sS, sC, sO;

    const int tid = threadIdx.x;
    const int i   = blockIdx.x * 256 + tid;

    // Prefetch this thread's element FIRST: its ~577-cycle DRAM latency
    // runs concurrently with the scan below.
    const bool valid = (i < n4);
    float4 v;
    if (valid) v = x4[i];

    // ---- warp 0: parallel-load + shuffle scan over up to 128 layers ----
    if (tid < 32) {
        float S = 1.0f, C = -FLT_MAX, O = 0.0f;
        #pragma unroll
        for (int k = 0; k < 4; ++k) {
            const int idx = 4 * tid + k;          // independent loads: MLP=4
            if (idx < n_layers) {
                const float wi = w[idx];
                const float bi = b[idx];
                const float Cl = __fdividef(-bi, wi);
                C = fmaxf(C, __fdividef(Cl - O, S));
                S = wi * S;
                O = fmaf(wi, O, bi);
            }
        }
        #pragma unroll
        for (int d = 1; d < 32; d <<= 1) {
            const float Sp = __shfl_up_sync(0xffffffffu, S, d);
            const float Cp = __shfl_up_sync(0xffffffffu, C, d);
            const float Op = __shfl_up_sync(0xffffffffu, O, d);
            if (tid >= d) {
                C = fmaxf(Cp, __fdividef(C - Op, Sp));
                O = fmaf(S, Op, O);   // uses pre-update S
                S = S * Sp;
            }
        }
        if (tid == 31) { sS = S; sC = C; sO = O; }
    }
    __syncthreads();

    const float S = sS;
    const float C = sC;
    const float O = sO;

    if (valid) {
        float4 r;
        r.x = fmaf(S, fmaxf(v.x, C), O);
        r.y = fmaf(S, fmaxf(v.y, C), O);
        r.z = fmaf(S, fmaxf(v.z, C), O);
        r.w = fmaf(S, fmaxf(v.w, C), O);
        o4[i] = r;
    }

    // scalar tail (n % 4 != 0) — negligible
    if (blockIdx.x == 0 && tid == 0) {
        for (int j = n4 * 4; j < n; ++j) {
            out[j] = fmaf(S, fmaxf(x[j], C), O);
        }
    }
}

extern "C" void kernel_launch(void* const* d_in, const int* in_sizes, int n_in,
                              void* d_out, int out_size) {
    const float* x = (const float*)d_in[0];
    const float* w = (const float*)d_in[1];
    const float* b = (const float*)d_in[2];
    float* out = (float*)d_out;

    const int n        = in_sizes[0];
    const int n_layers = in_sizes[1];
    const int n4       = n / 4;

    const int threads = 256;
    const int blocks  = (n4 + threads - 1) / threads;  // flat: 1 float4/thread

    fused_flat_kernel<<<blocks, threads>>>(
        (const float4*)x, (float4*)out, w, b, n_layers, n4, n, x, out);
}

// round 5
// speedup vs baseline: 1.1526x; 1.0099x over previous
#include <cuda_runtime.h>
#include <cfloat>

// 101-layer chain h <- relu(w*h + b), w > 0, collapses exactly to
//   f(x) = S * max(x, C) + O.
// The prefix triple (S, C, O) composes associatively:
//   (g o f): S = Sg*Sf,  C = max(Cf, (Cg - Of)/Sf),  O = Sg*Of + Og.
//
// R5: flat kernel, TWO float4 per thread (contiguous block tile of 512
// float4s). Halves the number of per-block scans/barriers vs R4 and doubles
// per-thread MLP during the scan window. Warp 0's shuffle scan is hidden
// under the two prefetched DRAM loads.

__global__ __launch_bounds__(256, 8)
void fused_flat2_kernel(const float4* __restrict__ x4,
                        float4* __restrict__ o4,
                        const float* __restrict__ w,
                        const float* __restrict__ b,
                        int n_layers, int n4, int n,
                        const float* __restrict__ x,
                        float* __restrict__ out) {
    __shared__ float sS, sC, sO;

    const int tid = threadIdx.x;
    const int i0  = blockIdx.x * 512 + tid;
    const int i1  = i0 + 256;

    // Prefetch both elements FIRST: their DRAM latency overlaps the scan.
    const bool v0ok = (i0 < n4);
    const bool v1ok = (i1 < n4);
    float4 v0, v1;
    if (v0ok) v0 = x4[i0];
    if (v1ok) v1 = x4[i1];

    // ---- warp 0: parallel-load + shuffle scan over up to 128 layers ----
    if (tid < 32) {
        float S = 1.0f, C = -FLT_MAX, O = 0.0f;
        #pragma unroll
        for (int k = 0; k < 4; ++k) {
            const int idx = 4 * tid + k;          // independent loads
            if (idx < n_layers) {
                const float wi = w[idx];
                const float bi = b[idx];
                const float Cl = __fdividef(-bi, wi);
                C = fmaxf(C, __fdividef(Cl - O, S));
                S = wi * S;
                O = fmaf(wi, O, bi);
            }
        }
        #pragma unroll
        for (int d = 1; d < 32; d <<= 1) {
            const float Sp = __shfl_up_sync(0xffffffffu, S, d);
            const float Cp = __shfl_up_sync(0xffffffffu, C, d);
            const float Op = __shfl_up_sync(0xffffffffu, O, d);
            if (tid >= d) {
                C = fmaxf(Cp, __fdividef(C - Op, Sp));
                O = fmaf(S, Op, O);   // uses pre-update S
                S = S * Sp;
            }
        }
        if (tid == 31) { sS = S; sC = C; sO = O; }
    }
    __syncthreads();

    const float S = sS;
    const float C = sC;
    const float O = sO;

    if (v0ok) {
        float4 r;
        r.x = fmaf(S, fmaxf(v0.x, C), O);
        r.y = fmaf(S, fmaxf(v0.y, C), O);
        r.z = fmaf(S, fmaxf(v0.z, C), O);
        r.w = fmaf(S, fmaxf(v0.w, C), O);
        o4[i0] = r;
    }
    if (v1ok) {
        float4 r;
        r.x = fmaf(S, fmaxf(v1.x, C), O);
        r.y = fmaf(S, fmaxf(v1.y, C), O);
        r.z = fmaf(S, fmaxf(v1.z, C), O);
        r.w = fmaf(S, fmaxf(v1.w, C), O);
        o4[i1] = r;
    }

    // scalar tail (n % 4 != 0) — negligible
    if (blockIdx.x == 0 && tid == 0) {
        for (int j = n4 * 4; j < n; ++j) {
            out[j] = fmaf(S, fmaxf(x[j], C), O);
        }
    }
}

extern "C" void kernel_launch(void* const* d_in, const int* in_sizes, int n_in,
                              void* d_out, int out_size) {
    const float* x = (const float*)d_in[0];
    const float* w = (const float*)d_in[1];
    const float* b = (const float*)d_in[2];
    float* out = (float*)d_out;

    const int n        = in_sizes[0];
    const int n_layers = in_sizes[1];
    const int n4       = n / 4;

    const int threads = 256;
    const int blocks  = (n4 + 511) / 512;   // 2 float4 per thread

    fused_flat2_kernel<<<blocks, threads>>>(
        (const float4*)x, (float4*)out, w, b, n_layers, n4, n, x, out);
}

// round 6
// speedup vs baseline: 1.1950x; 1.0368x over previous
#include <cuda_runtime.h>
#include <cfloat>

// 101-layer chain h <- relu(w*h + b), w > 0, collapses exactly to
//   f(x) = S * max(x, C) + O.
// Prefix triples (S, C, O) compose associatively:
//   (g o f): S = Sg*Sf,  C = max(Cf, (Cg - Of)/Sf),  O = Sg*Of + Og.
//
// R6: flat kernel, FOUR float4 per thread (contiguous block tile of 1024
// float4s). All 4 loads are issued before the scan/barrier (MLP=4 in the
// scan shadow); 8192 blocks -> 4x fewer redundant scans than R4.

__global__ __launch_bounds__(256)
void fused_flat4_kernel(const float4* __restrict__ x4,
                        float4* __restrict__ o4,
                        const float* __restrict__ w,
                        const float* __restrict__ b,
                        int n_layers, int n4, int n,
                        const float* __restrict__ x,
                        float* __restrict__ out) {
    __shared__ float sS, sC, sO;

    const int tid  = threadIdx.x;
    const int base = blockIdx.x * 1024 + tid;

    // Prefetch all four elements FIRST: DRAM latency overlaps the scan.
    float4 v0, v1, v2, v3;
    const bool ok0 = (base           < n4);
    const bool ok1 = (base + 256     < n4);
    const bool ok2 = (base + 512     < n4);
    const bool ok3 = (base + 768     < n4);
    if (ok0) v0 = x4[base];
    if (ok1) v1 = x4[base + 256];
    if (ok2) v2 = x4[base + 512];
    if (ok3) v3 = x4[base + 768];

    // ---- warp 0: parallel-load + shuffle scan over up to 128 layers ----
    if (tid < 32) {
        float S = 1.0f, C = -FLT_MAX, O = 0.0f;
        #pragma unroll
        for (int k = 0; k < 4; ++k) {
            const int idx = 4 * tid + k;          // independent loads
            if (idx < n_layers) {
                const float wi = w[idx];
                const float bi = b[idx];
                const float Cl = __fdividef(-bi, wi);
                C = fmaxf(C, __fdividef(Cl - O, S));
                S = wi * S;
                O = fmaf(wi, O, bi);
            }
        }
        #pragma unroll
        for (int d = 1; d < 32; d <<= 1) {
            const float Sp = __shfl_up_sync(0xffffffffu, S, d);
            const float Cp = __shfl_up_sync(0xffffffffu, C, d);
            const float Op = __shfl_up_sync(0xffffffffu, O, d);
            if (tid >= d) {
                C = fmaxf(Cp, __fdividef(C - Op, Sp));
                O = fmaf(S, Op, O);   // uses pre-update S
                S = S * Sp;
            }
        }
        if (tid == 31) { sS = S; sC = C; sO = O; }
    }
    __syncthreads();

    const float S = sS;
    const float C = sC;
    const float O = sO;

    float4 r;
    if (ok0) {
        r.x = fmaf(S, fmaxf(v0.x, C), O); r.y = fmaf(S, fmaxf(v0.y, C), O);
        r.z = fmaf(S, fmaxf(v0.z, C), O); r.w = fmaf(S, fmaxf(v0.w, C), O);
        o4[base] = r;
    }
    if (ok1) {
        r.x = fmaf(S, fmaxf(v1.x, C), O); r.y = fmaf(S, fmaxf(v1.y, C), O);
        r.z = fmaf(S, fmaxf(v1.z, C), O); r.w = fmaf(S, fmaxf(v1.w, C), O);
        o4[base + 256] = r;
    }
    if (ok2) {
        r.x = fmaf(S, fmaxf(v2.x, C), O); r.y = fmaf(S, fmaxf(v2.y, C), O);
        r.z = fmaf(S, fmaxf(v2.z, C), O); r.w = fmaf(S, fmaxf(v2.w, C), O);
        o4[base + 512] = r;
    }
    if (ok3) {
        r.x = fmaf(S, fmaxf(v3.x, C), O); r.y = fmaf(S, fmaxf(v3.y, C), O);
        r.z = fmaf(S, fmaxf(v3.z, C), O); r.w = fmaf(S, fmaxf(v3.w, C), O);
        o4[base + 768] = r;
    }

    // scalar tail (n % 4 != 0) — negligible
    if (blockIdx.x == 0 && tid == 0) {
        for (int j = n4 * 4; j < n; ++j) {
            out[j] = fmaf(S, fmaxf(x[j], C), O);
        }
    }
}

extern "C" void kernel_launch(void* const* d_in, const int* in_sizes, int n_in,
                              void* d_out, int out_size) {
    const float* x = (const float*)d_in[0];
    const float* w = (const float*)d_in[1];
    const float* b = (const float*)d_in[2];
    float* out = (float*)d_out;

    const int n        = in_sizes[0];
    const int n_layers = in_sizes[1];
    const int n4       = n / 4;

    const int threads = 256;
    const int blocks  = (n4 + 1023) / 1024;   // 4 float4 per thread

    fused_flat4_kernel<<<blocks, threads>>>(
        (const float4*)x, (float4*)out, w, b, n_layers, n4, n, x, out);
}